// round 5
// baseline (speedup 1.0000x reference)
#include <cuda_runtime.h>
#include <cuda_bf16.h>

// RotaryPositionEncoding3D: out[B,N,192,2] f32 from xyz[B,N,3] f32 and div_term[32] f32.
// Each output float4 g = (cos, sin, cos, sin) of angle xyz[p, axis]*div_term[bin],
//   p = g/96, j = g%96, axis = j%3, bin = j/3.
//
// v5: v4 structure (8 float4s/thread, stride-256, closed-form per-k indices,
// front-batched independent LDG+MUFU chains) but DEFAULT stores instead of
// __stcs. v2(MLP=4) and v4(MLP=8) both plateaued at DRAM~73% with streaming
// stores -> MLP is no longer the limiter. Hypothesis: .cs evict-first makes L2
// drain dirty lines in small interleaved bursts, hurting DRAM row locality;
// default write-back accumulates larger contiguous bursts per slice.
// 402.6 MB stored; HBM-write-bound.

#define F4_PER_THREAD 8
#define THREADS 256
#define TILE (THREADS * F4_PER_THREAD)   // 2048 float4 per block

__global__ void __launch_bounds__(THREADS)
rope3d_kernel(const float* __restrict__ xyz,
              const float* __restrict__ div_term,
              float4* __restrict__ out,
              int total_f4) {
    const int base = blockIdx.x * TILE + threadIdx.x;

    const unsigned p0 = (unsigned)base / 96u;
    const unsigned j0 = (unsigned)base - p0 * 96u;   // [0, 96)

    float c[F4_PER_THREAD], s[F4_PER_THREAD];

#pragma unroll
    for (int k = 0; k < F4_PER_THREAD; ++k) {
        // Independent per-k index math: t < 96 + 7*256 = 1888
        unsigned t    = j0 + (unsigned)(k * THREADS);
        unsigned dp   = t / 96u;                     // small-range const div
        unsigned jk   = t - dp * 96u;                // j = 3*bin + axis
        unsigned bin  = jk / 3u;
        unsigned axis = jk - bin * 3u;

        float x  = __ldg(&xyz[(p0 + dp) * 3u + axis]);
        float dt = __ldg(&div_term[bin]);
        __sincosf(x * dt, &s[k], &c[k]);             // |ang| <= 1, ample precision
    }

#pragma unroll
    for (int k = 0; k < F4_PER_THREAD; ++k) {
        int g = base + k * THREADS;
        if (g < total_f4)
            out[g] = make_float4(c[k], s[k], c[k], s[k]);   // default write-back STG.128
    }
}

extern "C" void kernel_launch(void* const* d_in, const int* in_sizes, int n_in,
                              void* d_out, int out_size) {
    const float* xyz      = (const float*)d_in[0];
    const float* div_term = (const float*)d_in[1];
    float4* out = (float4*)d_out;

    int total_f4 = out_size / 4;                     // 25,165,824 for B=4, N=65536
    int blocks = (total_f4 + TILE - 1) / TILE;       // 12,288 (exact fit)
    rope3d_kernel<<<blocks, THREADS>>>(xyz, div_term, out, total_f4);
}